// round 3
// baseline (speedup 1.0000x reference)
#include <cuda_runtime.h>
#include <cstdint>

typedef unsigned long long u64;

#define HW 3136  // 56*56

// Intermediate T[l][m][n][i*4+j] : (128, 56, 56, 8) floats = 12.85 MB scratch
__device__ float g_T[128 * 56 * 56 * 8];

__device__ __forceinline__ u64 pack2(float a, float b) {
    u64 r; asm("mov.b64 %0, {%1,%2};" : "=l"(r) : "f"(a), "f"(b)); return r;
}
__device__ __forceinline__ float2 unpack2(u64 a) {
    float2 r; asm("mov.b64 {%0,%1}, %2;" : "=f"(r.x), "=f"(r.y) : "l"(a)); return r;
}
__device__ __forceinline__ u64 fma2(u64 a, u64 b, u64 c) {
    u64 d; asm("fma.rn.f32x2 %0, %1, %2, %3;" : "=l"(d) : "l"(a), "l"(b), "l"(c)); return d;
}

// ---------------------------------------------------------------------------
// K1: T[l,m,w, i*4+j] = sum_{kk<64, tap<3, valid} x[l, 2kk+i, rowof(m+tap-1), w] * w1[kk,tap,j]
//   rowof(hp) = (hp<=0) ? 55 : hp-1  (circular +1 roll); contribution 0 if hp outside [0,56)
//
// Thread = (l, m, w-quad). Block 112 = (wq:14, m:8). Grid (7 m-chunks, 64 l) per half.
// Lean register budget: 16 u64 acc + 2 float4 staging + 4 u64 weights.
// ---------------------------------------------------------------------------
__global__ __launch_bounds__(112, 8) void k1_stage1(const float* __restrict__ x,
                                                    const float* __restrict__ w1,
                                                    int l_base) {
    __shared__ u64 w1p[64 * 12];   // [kk*12 + tap*4 + j] = (w,w) dup pair
    int tid = threadIdx.x;
    for (int idx = tid; idx < 768; idx += 112) {
        float w = w1[idx];
        w1p[idx] = pack2(w, w);
    }
    __syncthreads();

    int wq = tid % 14;
    int mloc = tid / 14;               // 0..7
    int m  = blockIdx.x * 8 + mloc;    // 0..55
    int l  = blockIdx.y + l_base;
    int w0 = wq * 4;

    int  rows[3];
    bool val[3];
#pragma unroll
    for (int tap = 0; tap < 3; tap++) {
        int hp  = m + tap - 1;
        val[tap]  = (hp >= 0) && (hp < 56);
        rows[tap] = (hp <= 0) ? 55 : ((hp >= 56) ? 55 : hp - 1);
    }

    u64 acc[2][4][2];  // [i][j][wp]
#pragma unroll
    for (int i = 0; i < 2; i++)
#pragma unroll
        for (int j = 0; j < 4; j++)
#pragma unroll
            for (int wp = 0; wp < 2; wp++) acc[i][j][wp] = 0ull;

    const float* xb = x + (size_t)l * 128 * HW + w0;

#pragma unroll 2
    for (int kk = 0; kk < 64; kk++) {
        const float* c0 = xb + (size_t)(2 * kk) * HW;  // i=0 channel
#pragma unroll
        for (int tap = 0; tap < 3; tap++) {
            if (val[tap]) {
                // weights: 4 packed dup-pairs (LDS.128 x2, broadcast)
                ulonglong2 wa = *reinterpret_cast<const ulonglong2*>(&w1p[kk * 12 + tap * 4]);
                ulonglong2 wb = *reinterpret_cast<const ulonglong2*>(&w1p[kk * 12 + tap * 4 + 2]);
                u64 W[4] = {wa.x, wa.y, wb.x, wb.y};

                int off = rows[tap] * 56;
                ulonglong2 a = *reinterpret_cast<const ulonglong2*>(c0 + off);        // i=0
                ulonglong2 b = *reinterpret_cast<const ulonglong2*>(c0 + HW + off);   // i=1
#pragma unroll
                for (int j = 0; j < 4; j++) {
                    acc[0][j][0] = fma2(a.x, W[j], acc[0][j][0]);
                    acc[0][j][1] = fma2(a.y, W[j], acc[0][j][1]);
                    acc[1][j][0] = fma2(b.x, W[j], acc[1][j][0]);
                    acc[1][j][1] = fma2(b.y, W[j], acc[1][j][1]);
                }
            }
        }
    }

    // unpack and store: per w, 8 contiguous floats (i*4+j) = 2x STG.128
    float accf[2][4][2][2];  // [i][j][wp][we]
#pragma unroll
    for (int i = 0; i < 2; i++)
#pragma unroll
        for (int j = 0; j < 4; j++)
#pragma unroll
            for (int wp = 0; wp < 2; wp++) {
                float2 v = unpack2(acc[i][j][wp]);
                accf[i][j][wp][0] = v.x;
                accf[i][j][wp][1] = v.y;
            }

    float* Tp = g_T + (((size_t)l * 56 + m) * 56 + w0) * 8;
#pragma unroll
    for (int wp = 0; wp < 2; wp++)
#pragma unroll
        for (int we = 0; we < 2; we++) {
            int w = 2 * wp + we;
            *reinterpret_cast<float4*>(Tp + w * 8) =
                make_float4(accf[0][0][wp][we], accf[0][1][wp][we],
                            accf[0][2][wp][we], accf[0][3][wp][we]);
            *reinterpret_cast<float4*>(Tp + w * 8 + 4) =
                make_float4(accf[1][0][wp][we], accf[1][1][wp][we],
                            accf[1][2][wp][we], accf[1][3][wp][we]);
        }
}

// ---------------------------------------------------------------------------
// K2 (round-1 version, known 38.5us): out[l, 4j+oo, m, n] =
//     sum_{i2<2,k<3} T[l,m,n+k-1, i2*4+oo] * w2[i2,k,j]
// Thread = (l, m, nq). 196 blocks x 256 per l-half (64 l x 56 m x 14 nq = 50176).
// ---------------------------------------------------------------------------
__global__ __launch_bounds__(256) void k2_stage2(const float* __restrict__ w2,
                                                 float* __restrict__ out,
                                                 int l_base) {
    __shared__ float w2s[192];   // [i*96 + k*32 + j]
    int tid = threadIdx.x;
    if (tid < 192) w2s[tid] = w2[tid];
    __syncthreads();

    int gt  = blockIdx.x * 256 + tid;
    int nq  = gt % 14;
    int rem = gt / 14;
    int m   = rem % 56;
    int l   = rem / 56 + l_base;

    // load 6 T positions: n' = 4nq-1 .. 4nq+4
    float tv[6][8];
    const float* Tp = g_T + (((size_t)l * 56 + m) * 56) * 8;
#pragma unroll
    for (int s = 0; s < 6; s++) {
        int np = 4 * nq - 1 + s;
        if (np >= 0 && np < 56) {
            float4 a = *reinterpret_cast<const float4*>(Tp + np * 8);
            float4 b = *reinterpret_cast<const float4*>(Tp + np * 8 + 4);
            tv[s][0] = a.x; tv[s][1] = a.y; tv[s][2] = a.z; tv[s][3] = a.w;
            tv[s][4] = b.x; tv[s][5] = b.y; tv[s][6] = b.z; tv[s][7] = b.w;
        } else {
#pragma unroll
            for (int t = 0; t < 8; t++) tv[s][t] = 0.0f;
        }
    }

    float* ob = out + (size_t)l * 128 * HW + m * 56 + 4 * nq;

#pragma unroll 4
    for (int j = 0; j < 32; j++) {
        float wv[6];
#pragma unroll
        for (int i2 = 0; i2 < 2; i2++)
#pragma unroll
            for (int k = 0; k < 3; k++)
                wv[i2 * 3 + k] = w2s[i2 * 96 + k * 32 + j];

#pragma unroll
        for (int oo = 0; oo < 4; oo++) {
            float rr[4];
#pragma unroll
            for (int nn = 0; nn < 4; nn++) {
                float s = 0.0f;
#pragma unroll
                for (int i2 = 0; i2 < 2; i2++)
#pragma unroll
                    for (int k = 0; k < 3; k++)
                        s += tv[nn + k][i2 * 4 + oo] * wv[i2 * 3 + k];
                rr[nn] = s;
            }
            *reinterpret_cast<float4*>(ob + (size_t)(4 * j + oo) * HW) =
                make_float4(rr[0], rr[1], rr[2], rr[3]);
        }
    }
}

// ---------------------------------------------------------------------------
extern "C" void kernel_launch(void* const* d_in, const int* in_sizes, int n_in,
                              void* d_out, int out_size) {
    const float* x  = nullptr;
    const float* w1 = nullptr;
    const float* w2 = nullptr;
    for (int i = 0; i < n_in; i++) {
        if (in_sizes[i] == 128 * 128 * 56 * 56) x  = (const float*)d_in[i];
        else if (in_sizes[i] == 64 * 3 * 4)     w1 = (const float*)d_in[i];
        else if (in_sizes[i] == 2 * 3 * 32)     w2 = (const float*)d_in[i];
    }
    if (!x)  x  = (const float*)d_in[0];
    if (!w1) w1 = (const float*)d_in[1];
    if (!w2) w2 = (const float*)d_in[2];

    // 4-launch pattern so ncu (-s 5 -c 1) captures k1 (launch #6 = k1b)
    k1_stage1<<<dim3(7, 64), 112>>>(x, w1, 0);
    k1_stage1<<<dim3(7, 64), 112>>>(x, w1, 64);
    k2_stage2<<<196, 256>>>(w2, (float*)d_out, 0);
    k2_stage2<<<196, 256>>>(w2, (float*)d_out, 64);
}

// round 4
// speedup vs baseline: 1.6179x; 1.6179x over previous
#include <cuda_runtime.h>
#include <cstdint>

typedef unsigned long long u64;

#define HW 3136  // 56*56

// Intermediate T[l][m][n][i*4+j] : (128, 56, 56, 8) floats = 12.85 MB scratch
__device__ float g_T[128 * 56 * 56 * 8];

__device__ __forceinline__ u64 pack2(float a, float b) {
    u64 r; asm("mov.b64 %0, {%1,%2};" : "=l"(r) : "f"(a), "f"(b)); return r;
}
__device__ __forceinline__ float2 unpack2(u64 a) {
    float2 r; asm("mov.b64 {%0,%1}, %2;" : "=f"(r.x), "=f"(r.y) : "l"(a)); return r;
}
__device__ __forceinline__ u64 fma2(u64 a, u64 b, u64 c) {
    u64 d; asm("fma.rn.f32x2 %0, %1, %2, %3;" : "=l"(d) : "l"(a), "l"(b), "l"(c)); return d;
}

#define NSLOT 11   // rows m0-2 .. m0+7 (slots 0..9) + wrap row 55 (slot 10)
#define CCH 8      // channels per smem chunk

// ---------------------------------------------------------------------------
// K1: T[l,m,w, i*4+j] = sum_{kk<64, tap<3, valid} x[l, 2kk+i, hsrc, w] * w1[kk,tap,j]
//   hp = m+tap-1; valid iff hp in [0,56); hsrc = (hp==0) ? 55 : hp-1  (+1 circular roll)
//
// Block = (l, 8-row m chunk), 224 threads = pos(112 = wq14 x mloc8) x i-half(2).
// x staged through smem in 8-channel chunks with coalesced float4 loads.
// ---------------------------------------------------------------------------
__global__ __launch_bounds__(224) void k1_stage1(const float* __restrict__ x,
                                                 const float* __restrict__ w1) {
    __shared__ float xs[CCH * NSLOT * 56];   // [c][slot][w]  19712 B
    __shared__ u64   w1p[768];               // [kk*12 + tap*4 + j] dup-pair, 6144 B

    int tid = threadIdx.x;
    for (int idx = tid; idx < 768; idx += 224) {
        float w = w1[idx];
        w1p[idx] = pack2(w, w);
    }

    int pos  = tid % 112;
    int h    = tid / 112;        // i-half (output dim, no reduction)
    int wq   = pos % 14;
    int mloc = pos / 14;         // 0..7
    int m0   = blockIdx.x * 8;
    int l    = blockIdx.y;
    int m    = m0 + mloc;
    int w0   = wq * 4;

    // per-(m,tap) smem slot + validity
    int  slot[3];
    bool val[3];
#pragma unroll
    for (int tap = 0; tap < 3; tap++) {
        int hp   = m + tap - 1;
        val[tap] = (hp >= 0) && (hp < 56);
        slot[tap] = (hp == 0) ? 10 : (mloc + tap);
    }

    u64 acc[4][2];  // [j][w-pair]
#pragma unroll
    for (int j = 0; j < 4; j++) { acc[j][0] = 0ull; acc[j][1] = 0ull; }

    const float* xl = x + (size_t)l * 128 * HW;

    for (int ch = 0; ch < 16; ch++) {
        int c0 = ch * CCH;
        __syncthreads();   // previous compute done (also orders w1p init on iter 0)

        // cooperative coalesced tile load: 8 ch x 11 slots x 14 float4 = 1232 float4
        for (int idx = tid; idx < CCH * NSLOT * 14; idx += 224) {
            int c  = idx / (NSLOT * 14);
            int r  = idx % (NSLOT * 14);
            int s  = r / 14;
            int wf = r % 14;
            int row = (s == 10) ? 55 : min(max(m0 - 2 + s, 0), 55);
            float4 v = *reinterpret_cast<const float4*>(
                xl + (size_t)(c0 + c) * HW + row * 56 + wf * 4);
            *reinterpret_cast<float4*>(&xs[(c * NSLOT + s) * 56 + wf * 4]) = v;
        }
        __syncthreads();

#pragma unroll
        for (int kl = 0; kl < 4; kl++) {
            int kk = ch * 4 + kl;
            int cl = 2 * kl + h;   // channel within chunk for this i-half
#pragma unroll
            for (int tap = 0; tap < 3; tap++) {
                if (val[tap]) {
                    ulonglong2 wa = *reinterpret_cast<const ulonglong2*>(&w1p[kk * 12 + tap * 4]);
                    ulonglong2 wb = *reinterpret_cast<const ulonglong2*>(&w1p[kk * 12 + tap * 4 + 2]);
                    ulonglong2 xp = *reinterpret_cast<const ulonglong2*>(
                        &xs[(cl * NSLOT + slot[tap]) * 56 + w0]);
                    acc[0][0] = fma2(xp.x, wa.x, acc[0][0]);
                    acc[0][1] = fma2(xp.y, wa.x, acc[0][1]);
                    acc[1][0] = fma2(xp.x, wa.y, acc[1][0]);
                    acc[1][1] = fma2(xp.y, wa.y, acc[1][1]);
                    acc[2][0] = fma2(xp.x, wb.x, acc[2][0]);
                    acc[2][1] = fma2(xp.y, wb.x, acc[2][1]);
                    acc[3][0] = fma2(xp.x, wb.y, acc[3][0]);
                    acc[3][1] = fma2(xp.y, wb.y, acc[3][1]);
                }
            }
        }
    }

    // store: per w, float4 of j values at T[..][w][h*4 + j]
    float* Tp = g_T + (((size_t)l * 56 + m) * 56 + w0) * 8 + h * 4;
#pragma unroll
    for (int wp = 0; wp < 2; wp++) {
        float2 j0 = unpack2(acc[0][wp]);
        float2 j1 = unpack2(acc[1][wp]);
        float2 j2 = unpack2(acc[2][wp]);
        float2 j3 = unpack2(acc[3][wp]);
        *reinterpret_cast<float4*>(Tp + (2 * wp + 0) * 8) = make_float4(j0.x, j1.x, j2.x, j3.x);
        *reinterpret_cast<float4*>(Tp + (2 * wp + 1) * 8) = make_float4(j0.y, j1.y, j2.y, j3.y);
    }
}

// ---------------------------------------------------------------------------
// K2 (round-1 version, known-good 38.5us): out[l, 4j+oo, m, n] =
//     sum_{i2<2,k<3} T[l,m,n+k-1, i2*4+oo] * w2[i2,k,j]
// Thread = (l, m, nq). 392 blocks x 256 = 100352 threads (exact).
// ---------------------------------------------------------------------------
__global__ __launch_bounds__(256) void k2_stage2(const float* __restrict__ w2,
                                                 float* __restrict__ out) {
    __shared__ float w2s[192];   // [i*96 + k*32 + j]
    int tid = threadIdx.x;
    if (tid < 192) w2s[tid] = w2[tid];
    __syncthreads();

    int gt  = blockIdx.x * 256 + tid;
    int nq  = gt % 14;
    int rem = gt / 14;
    int m   = rem % 56;
    int l   = rem / 56;

    float tv[6][8];
    const float* Tp = g_T + (((size_t)l * 56 + m) * 56) * 8;
#pragma unroll
    for (int s = 0; s < 6; s++) {
        int np = 4 * nq - 1 + s;
        if (np >= 0 && np < 56) {
            float4 a = *reinterpret_cast<const float4*>(Tp + np * 8);
            float4 b = *reinterpret_cast<const float4*>(Tp + np * 8 + 4);
            tv[s][0] = a.x; tv[s][1] = a.y; tv[s][2] = a.z; tv[s][3] = a.w;
            tv[s][4] = b.x; tv[s][5] = b.y; tv[s][6] = b.z; tv[s][7] = b.w;
        } else {
#pragma unroll
            for (int t = 0; t < 8; t++) tv[s][t] = 0.0f;
        }
    }

    float* ob = out + (size_t)l * 128 * HW + m * 56 + 4 * nq;

#pragma unroll 4
    for (int j = 0; j < 32; j++) {
        float wv[6];
#pragma unroll
        for (int i2 = 0; i2 < 2; i2++)
#pragma unroll
            for (int k = 0; k < 3; k++)
                wv[i2 * 3 + k] = w2s[i2 * 96 + k * 32 + j];

#pragma unroll
        for (int oo = 0; oo < 4; oo++) {
            float rr[4];
#pragma unroll
            for (int nn = 0; nn < 4; nn++) {
                float s = 0.0f;
#pragma unroll
                for (int i2 = 0; i2 < 2; i2++)
#pragma unroll
                    for (int k = 0; k < 3; k++)
                        s += tv[nn + k][i2 * 4 + oo] * wv[i2 * 3 + k];
                rr[nn] = s;
            }
            *reinterpret_cast<float4*>(ob + (size_t)(4 * j + oo) * HW) =
                make_float4(rr[0], rr[1], rr[2], rr[3]);
        }
    }
}

// ---------------------------------------------------------------------------
extern "C" void kernel_launch(void* const* d_in, const int* in_sizes, int n_in,
                              void* d_out, int out_size) {
    const float* x  = nullptr;
    const float* w1 = nullptr;
    const float* w2 = nullptr;
    for (int i = 0; i < n_in; i++) {
        if (in_sizes[i] == 128 * 128 * 56 * 56) x  = (const float*)d_in[i];
        else if (in_sizes[i] == 64 * 3 * 4)     w1 = (const float*)d_in[i];
        else if (in_sizes[i] == 2 * 3 * 32)     w2 = (const float*)d_in[i];
    }
    if (!x)  x  = (const float*)d_in[0];
    if (!w1) w1 = (const float*)d_in[1];
    if (!w2) w2 = (const float*)d_in[2];

    k1_stage1<<<dim3(7, 128), 224>>>(x, w1);
    k2_stage2<<<392, 256>>>(w2, (float*)d_out);
}

// round 8
// speedup vs baseline: 2.1549x; 1.3319x over previous
#include <cuda_runtime.h>
#include <cstdint>

typedef unsigned long long u64;

#define HW 3136  // 56*56

__device__ __forceinline__ u64 pack2(float a, float b) {
    u64 r; asm("mov.b64 %0, {%1,%2};" : "=l"(r) : "f"(a), "f"(b)); return r;
}
__device__ __forceinline__ float2 unpack2(u64 a) {
    float2 r; asm("mov.b64 {%0,%1}, %2;" : "=f"(r.x), "=f"(r.y) : "l"(a)); return r;
}
__device__ __forceinline__ u64 fma2(u64 a, u64 b, u64 c) {
    u64 d; asm("fma.rn.f32x2 %0, %1, %2, %3;" : "=l"(d) : "l"(a), "l"(b), "l"(c)); return d;
}
__device__ __forceinline__ void cpa16(uint32_t dst, const void* src) {
    asm volatile("cp.async.cg.shared.global [%0], [%1], 16;" :: "r"(dst), "l"(src));
}
__device__ __forceinline__ void cpa_commit() { asm volatile("cp.async.commit_group;" ::: "memory"); }
__device__ __forceinline__ void cpa_wait0()  { asm volatile("cp.async.wait_group 0;"  ::: "memory"); }

#define NSLOT 11          // source rows m0-2..m0+7 (slots 0..9) + wrap row 55 (slot 10)
#define CCH 4             // channels per chunk
#define XS_CH (NSLOT * 56)
#define XS_BUF (CCH * XS_CH)      // 2464 floats
#define NLOAD (CCH * NSLOT * 14)  // 616 float4 per chunk

// ---------------------------------------------------------------------------
// Fused: block = (l, 8-row m chunk). 224 threads = (wq:14, mloc:8, h:2).
// Phase 1 (stage 1): x staged via double-buffered cp.async; packed f32x2 FMA;
//   result T tile kept in smem Ts[mi][ij][64] (col = 4 + w, edge cols zero).
// Phase 2 (stage 2): 3-tap conv along w from Ts, packed f32x2 over the i2
//   reduction (weights pre-packed as (i2=0,i2=1) pairs), halves summed at end.
// ---------------------------------------------------------------------------
__global__ __launch_bounds__(224, 4) void fused(const float* __restrict__ x,
                                                const float* __restrict__ w1,
                                                const float* __restrict__ w2,
                                                float* __restrict__ out) {
    __shared__ float xs[2][XS_BUF];   // 19712 B
    __shared__ u64   w1p[768];        // stage-1 weights, (w,w) dup pairs     6144 B
    __shared__ u64   w2p[96];         // stage-2 weights, (i2=0,i2=1) pairs    768 B
    __shared__ float Ts[8 * 8 * 64];  // [mi][ij][4+w], 16384 B

    int tid = threadIdx.x;
    int m0  = blockIdx.x * 8;
    int l   = blockIdx.y;

    // ---- weights + Ts edge zeroing ----
    for (int i = tid; i < 768; i += 224) { float w = w1[i]; w1p[i] = pack2(w, w); }
    if (tid < 96) w2p[tid] = pack2(w2[tid], w2[96 + tid]);
    for (int i = tid; i < 64 * 8; i += 224) {       // 64 rows x 8 edge cols
        int r = i >> 3, c = i & 7;
        Ts[r * 64 + (c < 4 ? c : 56 + c)] = 0.0f;   // cols 0..3 and 60..63
    }

    // ---- thread decode (shared by both phases) ----
    int wq   = tid % 14;
    int mloc = (tid / 14) % 8;
    int h    = tid / 112;        // i-half in phase 1, j-half in phase 2
    int m    = m0 + mloc;
    int w0   = wq * 4;

    // per-(m,tap) smem slot + validity (stage-1 H taps with +1 circular roll)
    int  slot[3];
    bool val[3];
#pragma unroll
    for (int tap = 0; tap < 3; tap++) {
        int hp    = m + tap - 1;
        val[tap]  = (hp >= 0) && (hp < 56);
        slot[tap] = (hp == 0) ? 10 : (mloc + tap);
    }

    // ---- cooperative-loader precompute: 3 slots/thread, address math hoisted ----
    const float* xl = x + (size_t)l * 128 * HW;
    int  goff[3];      // gmem float offset within a chunk (relative to chunk base)
    int  soff[3];      // smem byte offset within one buffer
    bool lv[3];
#pragma unroll
    for (int k = 0; k < 3; k++) {
        int idx = tid + k * 224;
        lv[k] = idx < NLOAD;
        int ii = lv[k] ? idx : 0;
        int c  = ii / (NSLOT * 14);
        int r  = ii % (NSLOT * 14);
        int s  = r / 14;
        int wf = r % 14;
        int row = (s == 10) ? 55 : min(max(m0 - 2 + s, 0), 55);
        goff[k] = c * HW + row * 56 + wf * 4;
        soff[k] = ((c * NSLOT + s) * 56 + wf * 4) * 4;
    }
    uint32_t xsb[2] = { (uint32_t)__cvta_generic_to_shared(&xs[0][0]),
                        (uint32_t)__cvta_generic_to_shared(&xs[1][0]) };

    u64 acc[4][2];  // [j][w-pair]
#pragma unroll
    for (int j = 0; j < 4; j++) { acc[j][0] = 0ull; acc[j][1] = 0ull; }

    // prefetch chunk 0
#pragma unroll
    for (int k = 0; k < 3; k++)
        if (lv[k]) cpa16(xsb[0] + soff[k], xl + goff[k]);
    cpa_commit();

    // ---- phase 1 main loop: 32 chunks of 4 channels ----
    for (int ch = 0; ch < 32; ch++) {
        cpa_wait0();
        __syncthreads();               // data visible to all; prev buf free
        if (ch < 31) {
            const float* cb = xl + (size_t)(ch + 1) * CCH * HW;
            uint32_t sb = xsb[(ch + 1) & 1];
#pragma unroll
            for (int k = 0; k < 3; k++)
                if (lv[k]) cpa16(sb + soff[k], cb + goff[k]);
            cpa_commit();
        }
        const float* xb = xs[ch & 1];
#pragma unroll
        for (int kl = 0; kl < 2; kl++) {
            int kk = ch * 2 + kl;
            int cl = 2 * kl + h;
#pragma unroll
            for (int tap = 0; tap < 3; tap++) {
                if (val[tap]) {
                    ulonglong2 wa = *reinterpret_cast<const ulonglong2*>(&w1p[kk * 12 + tap * 4]);
                    ulonglong2 wb = *reinterpret_cast<const ulonglong2*>(&w1p[kk * 12 + tap * 4 + 2]);
                    ulonglong2 xp = *reinterpret_cast<const ulonglong2*>(
                        &xb[(cl * NSLOT + slot[tap]) * 56 + w0]);
                    acc[0][0] = fma2(xp.x, wa.x, acc[0][0]);
                    acc[0][1] = fma2(xp.y, wa.x, acc[0][1]);
                    acc[1][0] = fma2(xp.x, wa.y, acc[1][0]);
                    acc[1][1] = fma2(xp.y, wa.y, acc[1][1]);
                    acc[2][0] = fma2(xp.x, wb.x, acc[2][0]);
                    acc[2][1] = fma2(xp.y, wb.x, acc[2][1]);
                    acc[3][0] = fma2(xp.x, wb.y, acc[3][0]);
                    acc[3][1] = fma2(xp.y, wb.y, acc[3][1]);
                }
            }
        }
    }

    // ---- write T tile to smem: Ts[mloc][ij][4 + w] ----
#pragma unroll
    for (int j = 0; j < 4; j++) {
        float2 a0 = unpack2(acc[j][0]);   // w0, w0+1
        float2 a1 = unpack2(acc[j][1]);   // w0+2, w0+3
        int ij = h * 4 + j;
        *reinterpret_cast<float4*>(&Ts[(mloc * 8 + ij) * 64 + 4 + w0]) =
            make_float4(a0.x, a0.y, a1.x, a1.y);
    }
    __syncthreads();

    // ---- phase 2: thread = (mloc, nq=wq, jh=h) covers n = 4nq..4nq+3, 16 j ----
    float* ob = out + (size_t)l * 128 * HW + m * 56 + w0;   // m=m0+mloc, w0=4*nq

#pragma unroll
    for (int p = 0; p < 2; p++) {        // oo pair: {2p, 2p+1}
        u64 pvt[2][6];                   // [ol][s], halves = (i2=0, i2=1)
#pragma unroll
        for (int ol = 0; ol < 2; ol++) {
            int oo = 2 * p + ol;
            const float* r0 = &Ts[(mloc * 8 + oo)     * 64 + 3 + w0];  // i2=0
            const float* r1 = &Ts[(mloc * 8 + 4 + oo) * 64 + 3 + w0];  // i2=1
#pragma unroll
            for (int s = 0; s < 6; s++) pvt[ol][s] = pack2(r0[s], r1[s]);
        }

#pragma unroll 4
        for (int jj = 0; jj < 16; jj++) {
            int j = h * 16 + jj;
            u64 wp0 = w2p[j], wp1 = w2p[32 + j], wp2 = w2p[64 + j];
#pragma unroll
            for (int ol = 0; ol < 2; ol++) {
                u64 rr[4];
#pragma unroll
                for (int nn = 0; nn < 4; nn++) {
                    u64 r = fma2(pvt[ol][nn], wp0, 0ull);
                    r = fma2(pvt[ol][nn + 1], wp1, r);
                    r = fma2(pvt[ol][nn + 2], wp2, r);
                    rr[nn] = r;
                }
                float2 e0 = unpack2(rr[0]), e1 = unpack2(rr[1]);
                float2 e2 = unpack2(rr[2]), e3 = unpack2(rr[3]);
                *reinterpret_cast<float4*>(ob + (size_t)(4 * j + 2 * p + ol) * HW) =
                    make_float4(e0.x + e0.y, e1.x + e1.y, e2.x + e2.y, e3.x + e3.y);
            }
        }
    }
}

// ---------------------------------------------------------------------------
extern "C" void kernel_launch(void* const* d_in, const int* in_sizes, int n_in,
                              void* d_out, int out_size) {
    const float* x  = nullptr;
    const float* w1 = nullptr;
    const float* w2 = nullptr;
    for (int i = 0; i < n_in; i++) {
        if (in_sizes[i] == 128 * 128 * 56 * 56) x  = (const float*)d_in[i];
        else if (in_sizes[i] == 64 * 3 * 4)     w1 = (const float*)d_in[i];
        else if (in_sizes[i] == 2 * 3 * 32)     w2 = (const float*)d_in[i];
    }
    if (!x)  x  = (const float*)d_in[0];
    if (!w1) w1 = (const float*)d_in[1];
    if (!w2) w2 = (const float*)d_in[2];

    fused<<<dim3(7, 128), 224>>>(x, w1, w2, (float*)d_out);
}

// round 9
// speedup vs baseline: 2.2393x; 1.0392x over previous
#include <cuda_runtime.h>
#include <cstdint>

typedef unsigned long long u64;

#define HW 3136  // 56*56

__device__ __forceinline__ u64 pack2(float a, float b) {
    u64 r; asm("mov.b64 %0, {%1,%2};" : "=l"(r) : "f"(a), "f"(b)); return r;
}
__device__ __forceinline__ float2 unpack2(u64 a) {
    float2 r; asm("mov.b64 {%0,%1}, %2;" : "=f"(r.x), "=f"(r.y) : "l"(a)); return r;
}
__device__ __forceinline__ u64 fma2(u64 a, u64 b, u64 c) {
    u64 d; asm("fma.rn.f32x2 %0, %1, %2, %3;" : "=l"(d) : "l"(a), "l"(b), "l"(c)); return d;
}
__device__ __forceinline__ void cpa16(uint32_t dst, const void* src) {
    asm volatile("cp.async.cg.shared.global [%0], [%1], 16;" :: "r"(dst), "l"(src));
}
__device__ __forceinline__ void cpa_commit() { asm volatile("cp.async.commit_group;" ::: "memory"); }
__device__ __forceinline__ void cpa_wait0()  { asm volatile("cp.async.wait_group 0;"  ::: "memory"); }
__device__ __forceinline__ void stcs4(float* p, float4 v) {
    asm volatile("st.global.cs.v4.f32 [%0], {%1,%2,%3,%4};"
                 :: "l"(p), "f"(v.x), "f"(v.y), "f"(v.z), "f"(v.w) : "memory");
}

#define NSLOT 11          // source rows m0-2..m0+7 (slots 0..9) + wrap row 55 (slot 10)
#define CCH 4             // channels per chunk
#define XS_CH (NSLOT * 56)
#define XS_BUF (CCH * XS_CH)      // 2464 floats
#define NLOAD (CCH * NSLOT * 14)  // 616 float4 per chunk

// ---------------------------------------------------------------------------
// Fused: block = (l, 8-row m chunk). 224 threads = (wq:14, mloc:8, h:2).
// Phase 1 (stage 1): x staged via double-buffered cp.async; packed f32x2 FMA;
//   result T tile kept in smem Ts[mi][ij][64] (col = 4 + w, edge cols zero).
// Phase 2 (stage 2): 3-tap conv along w from Ts, packed f32x2 over the i2
//   reduction; streaming stores (.cs) so output doesn't evict x halo in L2.
// 5 blocks/SM: regs capped at 58, smem 43008 B x 5 = 215K <= 228K.
// ---------------------------------------------------------------------------
__global__ __launch_bounds__(224, 5) void fused(const float* __restrict__ x,
                                                const float* __restrict__ w1,
                                                const float* __restrict__ w2,
                                                float* __restrict__ out) {
    __shared__ float xs[2][XS_BUF];   // 19712 B
    __shared__ u64   w1p[768];        // stage-1 weights, (w,w) dup pairs     6144 B
    __shared__ u64   w2p[96];         // stage-2 weights, (i2=0,i2=1) pairs    768 B
    __shared__ float Ts[8 * 8 * 64];  // [mi][ij][4+w], 16384 B

    int tid = threadIdx.x;
    int m0  = blockIdx.x * 8;
    int l   = blockIdx.y;

    // ---- weights + Ts edge zeroing ----
    for (int i = tid; i < 768; i += 224) { float w = w1[i]; w1p[i] = pack2(w, w); }
    if (tid < 96) w2p[tid] = pack2(w2[tid], w2[96 + tid]);
    for (int i = tid; i < 64 * 8; i += 224) {       // 64 rows x 8 edge cols
        int r = i >> 3, c = i & 7;
        Ts[r * 64 + (c < 4 ? c : 56 + c)] = 0.0f;   // cols 0..3 and 60..63
    }

    // ---- thread decode (shared by both phases) ----
    int wq   = tid % 14;
    int mloc = (tid / 14) % 8;
    int h    = tid / 112;        // i-half in phase 1, j-half in phase 2
    int m    = m0 + mloc;
    int w0   = wq * 4;

    // per-(m,tap) smem slot + validity (stage-1 H taps with +1 circular roll)
    int  slot[3];
    bool val[3];
#pragma unroll
    for (int tap = 0; tap < 3; tap++) {
        int hp    = m + tap - 1;
        val[tap]  = (hp >= 0) && (hp < 56);
        slot[tap] = (hp == 0) ? 10 : (mloc + tap);
    }

    // ---- cooperative-loader precompute: 3 slots/thread, address math hoisted ----
    const float* xl = x + (size_t)l * 128 * HW;
    int  goff[3];      // gmem float offset within a chunk (relative to chunk base)
    int  soff[3];      // smem byte offset within one buffer
    bool lv[3];
#pragma unroll
    for (int k = 0; k < 3; k++) {
        int idx = tid + k * 224;
        lv[k] = idx < NLOAD;
        int ii = lv[k] ? idx : 0;
        int c  = ii / (NSLOT * 14);
        int r  = ii % (NSLOT * 14);
        int s  = r / 14;
        int wf = r % 14;
        int row = (s == 10) ? 55 : min(max(m0 - 2 + s, 0), 55);
        goff[k] = c * HW + row * 56 + wf * 4;
        soff[k] = ((c * NSLOT + s) * 56 + wf * 4) * 4;
    }
    uint32_t xsb[2] = { (uint32_t)__cvta_generic_to_shared(&xs[0][0]),
                        (uint32_t)__cvta_generic_to_shared(&xs[1][0]) };

    u64 acc[4][2];  // [j][w-pair]
#pragma unroll
    for (int j = 0; j < 4; j++) { acc[j][0] = 0ull; acc[j][1] = 0ull; }

    // prefetch chunk 0
#pragma unroll
    for (int k = 0; k < 3; k++)
        if (lv[k]) cpa16(xsb[0] + soff[k], xl + goff[k]);
    cpa_commit();

    // ---- phase 1 main loop: 32 chunks of 4 channels ----
    for (int ch = 0; ch < 32; ch++) {
        cpa_wait0();
        __syncthreads();               // data visible to all; prev buf free
        if (ch < 31) {
            const float* cb = xl + (size_t)(ch + 1) * CCH * HW;
            uint32_t sb = xsb[(ch + 1) & 1];
#pragma unroll
            for (int k = 0; k < 3; k++)
                if (lv[k]) cpa16(sb + soff[k], cb + goff[k]);
            cpa_commit();
        }
        const float* xb = xs[ch & 1];
#pragma unroll
        for (int kl = 0; kl < 2; kl++) {
            int kk = ch * 2 + kl;
            int cl = 2 * kl + h;
#pragma unroll
            for (int tap = 0; tap < 3; tap++) {
                if (val[tap]) {
                    ulonglong2 wa = *reinterpret_cast<const ulonglong2*>(&w1p[kk * 12 + tap * 4]);
                    ulonglong2 wb = *reinterpret_cast<const ulonglong2*>(&w1p[kk * 12 + tap * 4 + 2]);
                    ulonglong2 xp = *reinterpret_cast<const ulonglong2*>(
                        &xb[(cl * NSLOT + slot[tap]) * 56 + w0]);
                    acc[0][0] = fma2(xp.x, wa.x, acc[0][0]);
                    acc[0][1] = fma2(xp.y, wa.x, acc[0][1]);
                    acc[1][0] = fma2(xp.x, wa.y, acc[1][0]);
                    acc[1][1] = fma2(xp.y, wa.y, acc[1][1]);
                    acc[2][0] = fma2(xp.x, wb.x, acc[2][0]);
                    acc[2][1] = fma2(xp.y, wb.x, acc[2][1]);
                    acc[3][0] = fma2(xp.x, wb.y, acc[3][0]);
                    acc[3][1] = fma2(xp.y, wb.y, acc[3][1]);
                }
            }
        }
    }

    // ---- write T tile to smem: Ts[mloc][ij][4 + w] ----
#pragma unroll
    for (int j = 0; j < 4; j++) {
        float2 a0 = unpack2(acc[j][0]);   // w0, w0+1
        float2 a1 = unpack2(acc[j][1]);   // w0+2, w0+3
        int ij = h * 4 + j;
        *reinterpret_cast<float4*>(&Ts[(mloc * 8 + ij) * 64 + 4 + w0]) =
            make_float4(a0.x, a0.y, a1.x, a1.y);
    }
    __syncthreads();

    // ---- phase 2: thread = (mloc, nq=wq, jh=h) covers n = 4nq..4nq+3, 16 j ----
    float* ob = out + (size_t)l * 128 * HW + m * 56 + w0;   // m=m0+mloc, w0=4*nq

#pragma unroll
    for (int p = 0; p < 2; p++) {        // oo pair: {2p, 2p+1}
        u64 pvt[2][6];                   // [ol][s], halves = (i2=0, i2=1)
#pragma unroll
        for (int ol = 0; ol < 2; ol++) {
            int oo = 2 * p + ol;
            const float* r0 = &Ts[(mloc * 8 + oo)     * 64 + 3 + w0];  // i2=0
            const float* r1 = &Ts[(mloc * 8 + 4 + oo) * 64 + 3 + w0];  // i2=1
#pragma unroll
            for (int s = 0; s < 6; s++) pvt[ol][s] = pack2(r0[s], r1[s]);
        }

#pragma unroll 4
        for (int jj = 0; jj < 16; jj++) {
            int j = h * 16 + jj;
            u64 wp0 = w2p[j], wp1 = w2p[32 + j], wp2 = w2p[64 + j];
#pragma unroll
            for (int ol = 0; ol < 2; ol++) {
                u64 rr[4];
#pragma unroll
                for (int nn = 0; nn < 4; nn++) {
                    u64 r = fma2(pvt[ol][nn], wp0, 0ull);
                    r = fma2(pvt[ol][nn + 1], wp1, r);
                    r = fma2(pvt[ol][nn + 2], wp2, r);
                    rr[nn] = r;
                }
                float2 e0 = unpack2(rr[0]), e1 = unpack2(rr[1]);
                float2 e2 = unpack2(rr[2]), e3 = unpack2(rr[3]);
                stcs4(ob + (size_t)(4 * j + 2 * p + ol) * HW,
                      make_float4(e0.x + e0.y, e1.x + e1.y, e2.x + e2.y, e3.x + e3.y));
            }
        }
    }
}

// ---------------------------------------------------------------------------
extern "C" void kernel_launch(void* const* d_in, const int* in_sizes, int n_in,
                              void* d_out, int out_size) {
    const float* x  = nullptr;
    const float* w1 = nullptr;
    const float* w2 = nullptr;
    for (int i = 0; i < n_in; i++) {
        if (in_sizes[i] == 128 * 128 * 56 * 56) x  = (const float*)d_in[i];
        else if (in_sizes[i] == 64 * 3 * 4)     w1 = (const float*)d_in[i];
        else if (in_sizes[i] == 2 * 3 * 32)     w2 = (const float*)d_in[i];
    }
    if (!x)  x  = (const float*)d_in[0];
    if (!w1) w1 = (const float*)d_in[1];
    if (!w2) w2 = (const float*)d_in[2];

    fused<<<dim3(7, 128), 224>>>(x, w1, w2, (float*)d_out);
}